// round 8
// baseline (speedup 1.0000x reference)
#include <cuda_runtime.h>

// MoreauTropicalKernel: B=128, N=512, D=1024. One warp per (b,n) pair.
// z = x[b]+W[n] resident as 16 packed f32x2 registers.
//  Pass1 @ taua = mx - lam: u = t+|t| = 2*relu -> fa, and exact slope
//    ka = #{z >= taua} (PRMT sign + dp4a).
//  Quadratic-Hermite root step: parabola through (taua,fa), slope -ka at taua,
//    and the free anchor (mx, 0); convexity => curvature c >= 0 and a root in
//    (taua, mx). Stable root: s = 2(fa-lam) / (ka + sqrt(ka^2 - 4c(fa-lam))).
//    tau2 = taua + s lies inside the [Newton-left, chord-right] bracket.
//  Pass2 @ tau2: f2, dsum = sum relu^2, exact k2; exact-segment closed form
//    y = tau2 + (dsum - (lam-f2)^2/k2) / (2*lam)  (valid from either side).
// Warp reductions: single-instruction REDUX (fixed-point sums; order-
// preserving uint map for max). 128-thread blocks for occupancy.

#define DDIM 1024
#define NDIM 512
#define ABSMASK 0x7FFFFFFF7FFFFFFFULL

typedef unsigned long long u64;

__device__ __forceinline__ u64 f32x2_add(u64 a, u64 b) {
    u64 r; asm("add.rn.f32x2 %0, %1, %2;" : "=l"(r) : "l"(a), "l"(b)); return r;
}
__device__ __forceinline__ u64 f32x2_fma(u64 a, u64 b, u64 c) {
    u64 r; asm("fma.rn.f32x2 %0, %1, %2, %3;" : "=l"(r) : "l"(a), "l"(b), "l"(c)); return r;
}
__device__ __forceinline__ u64 pack2(float lo, float hi) {
    u64 r; asm("mov.b64 %0, {%1, %2};" : "=l"(r) : "f"(lo), "f"(hi)); return r;
}
__device__ __forceinline__ float2 unpack2(u64 v) {
    float2 r; asm("mov.b64 {%0, %1}, %2;" : "=f"(r.x), "=f"(r.y) : "l"(v)); return r;
}
// cnt += -2 * (#negative floats in packed word t).
__device__ __forceinline__ void dp4a_sgn(u64 t, int& cnt) {
    unsigned lo, hi, p;
    asm("mov.b64 {%0, %1}, %2;" : "=r"(lo), "=r"(hi) : "l"(t));
    asm("prmt.b32 %0, %1, %2, 0xFBFB;" : "=r"(p) : "r"(lo), "r"(hi));
    asm("dp4a.s32.s32 %0, %1, %2, %0;" : "+r"(cnt) : "r"(p), "r"(0x01010101));
}
__device__ __forceinline__ float redux_fsum(float v, float scale, float inv) {
    int i = __float2int_rn(v * scale);
    unsigned s = __reduce_add_sync(0xffffffffu, (unsigned)i);
    return (float)(int)s * inv;
}
__device__ __forceinline__ unsigned fmap(float f) {
    unsigned u = __float_as_uint(f);
    return (u & 0x80000000u) ? ~u : (u | 0x80000000u);
}
__device__ __forceinline__ float funmap(unsigned m) {
    unsigned u = (m & 0x80000000u) ? (m ^ 0x80000000u) : ~m;
    return __uint_as_float(u);
}
__device__ __forceinline__ float fast_sqrt(float v) {
    float r; asm("sqrt.approx.f32 %0, %1;" : "=f"(r) : "f"(v)); return r;
}

__global__ __launch_bounds__(128)
void moreau_tropical_kernel(const float* __restrict__ x,
                            const float* __restrict__ W,
                            const float* __restrict__ lamp,
                            float* __restrict__ y,
                            int total_pairs) {
    int warp = (blockIdx.x * 128 + threadIdx.x) >> 5;
    if (warp >= total_pairs) return;
    int lane = threadIdx.x & 31;
    int b = warp >> 9;           // / NDIM
    int n = warp & (NDIM - 1);
    float lam = __ldg(lamp);

    const float4* xr = (const float4*)(x + (size_t)b * DDIM);
    const float4* wr = (const float4*)(W + (size_t)n * DDIM);

    u64 z[16];
    float mx = -3.4e38f;
#pragma unroll
    for (int j = 0; j < 8; j++) {
        float4 xv = xr[lane + 32 * j];
        float4 wv = wr[lane + 32 * j];
        u64 zp0 = f32x2_add(pack2(xv.x, xv.y), pack2(wv.x, wv.y));
        u64 zp1 = f32x2_add(pack2(xv.z, xv.w), pack2(wv.z, wv.w));
        z[2 * j]     = zp0;
        z[2 * j + 1] = zp1;
        float2 a = unpack2(zp0);
        float2 c = unpack2(zp1);
        mx = fmaxf(mx, fmaxf(fmaxf(a.x, a.y), fmaxf(c.x, c.y)));
    }
    mx = funmap(__reduce_max_sync(0xffffffffu, fmap(mx)));

    // Pass 1 @ taua = mx - lam: u = t + |t| = 2*relu; fa = sum(u)/2; ka count.
    float taua = mx - lam;
    u64 na = pack2(-taua, -taua);
    u64 ua0 = 0ull, ua1 = 0ull;
    int ca = 0;
#pragma unroll
    for (int j = 0; j < 16; j += 2) {
        u64 t0 = f32x2_add(z[j + 0], na);
        u64 t1 = f32x2_add(z[j + 1], na);
        u64 b0 = t0 & ABSMASK;
        u64 b1 = t1 & ABSMASK;
        ua0 = f32x2_add(ua0, f32x2_add(t0, b0));
        ua1 = f32x2_add(ua1, f32x2_add(t1, b1));
        dp4a_sgn(t0, ca);
        dp4a_sgn(t1, ca);
    }
    float2 uav = unpack2(f32x2_add(ua0, ua1));
    float fa = 0.5f * redux_fsum(uav.x + uav.y, 1048576.0f, 9.5367431640625e-7f); // 2^20
    int cta = (int)__reduce_add_sync(0xffffffffu, (unsigned)ca);   // -2 * #neg
    float ka = (float)(1024 + (cta >> 1));                         // >= 1

    // Quadratic-Hermite step: parabola q(taua+s) = fa - ka*s + c*s^2, q(mx)=0.
    // c = (ka*lam - fa)/lam^2 >= 0 (convexity); root exists in (0, lam].
    float fml = fa - lam;
    float c2q = __fdividef(ka * lam - fa, lam * lam);
    float disc = fmaf(-4.f * c2q, fml, ka * ka);
    float s = __fdividef(2.f * fml, ka + fast_sqrt(disc));
    float tau2 = fminf(fmaxf(taua + s, taua), mx);

    // Pass 2 (epilogue) @ tau2: f2, dsum = sum relu^2, k2 (merged accumulators).
    u64 nt = pack2(-tau2, -tau2);
    u64 us0 = 0ull, q0 = 0ull;
    int cc2 = 0;
#pragma unroll
    for (int j = 0; j < 16; j += 2) {
        u64 t0 = f32x2_add(z[j + 0], nt);
        u64 t1 = f32x2_add(z[j + 1], nt);
        u64 b0 = t0 & ABSMASK;
        u64 b1 = t1 & ABSMASK;
        u64 u0 = f32x2_add(t0, b0);
        u64 u1 = f32x2_add(t1, b1);
        us0 = f32x2_add(us0, f32x2_add(u0, u1));
        q0 = f32x2_fma(u0, u0, q0);
        q0 = f32x2_fma(u1, u1, q0);
        dp4a_sgn(t0, cc2);
        dp4a_sgn(t1, cc2);
    }
    float2 usv = unpack2(us0);
    float2 qv  = unpack2(q0);
    float f2 = 0.5f * redux_fsum(usv.x + usv.y, 1048576.0f, 9.5367431640625e-7f);  // 2^20
    float Us = redux_fsum(qv.x + qv.y, 2097152.0f, 4.76837158203125e-7f);          // 2^21
    int ct2 = (int)__reduce_add_sync(0xffffffffu, (unsigned)cc2);
    float k2 = (float)(1024 + (ct2 >> 1));                         // >= 1

    if (lane == 0) {
        float dsum = 0.25f * Us;
        float d = lam - f2;
        float corr = __fdividef(d * d, k2);
        y[warp] = tau2 + (dsum - corr) * __fdividef(0.5f, lam);
    }
}

extern "C" void kernel_launch(void* const* d_in, const int* in_sizes, int n_in,
                              void* d_out, int out_size) {
    const float* x   = (const float*)d_in[0];
    const float* W   = (const float*)d_in[1];
    const float* lam = (const float*)d_in[2];
    float* y = (float*)d_out;

    int B = in_sizes[0] / DDIM;      // 128
    int N = in_sizes[1] / DDIM;      // 512 (index math assumes 512)
    int pairs = B * N;               // 65536
    int blocks = (pairs + 3) / 4;    // 4 warps / block (128 threads)
    moreau_tropical_kernel<<<blocks, 128>>>(x, W, lam, y, pairs);
}

// round 10
// speedup vs baseline: 1.0137x; 1.0137x over previous
#include <cuda_runtime.h>
#include <cuda_fp16.h>

// MoreauTropicalKernel: B=128, N=512, D=1024. One warp per (b,n) pair.
// z = x[b]+W[n] resident as 16 packed f32x2 registers.
//  Pass1 (f16x2, cheap): at taua = mx - lam compute fa = sum relu(z-taua) and
//    slope ka = #{z >= taua}. f16 error only perturbs tau2 placement;
//    pass2's exact-segment correction absorbs it (error is 2nd order).
//    relu via max.f16x2 (1 instr / 2 vals); count via one PRMT sign-gather
//    over two f16x2 regs + dp4a (2 instr / 4 vals).
//  Quadratic-Hermite root step: parabola through (taua,fa), slope -ka, anchor
//    (mx,0) -> tau2 = taua + 2(fa-lam)/(ka + sqrt(ka^2-4c(fa-lam))),
//    c = (ka*lam-fa)/lam^2 >= 0 by convexity.
//  Pass2 (f32, exact): f2, dsum = sum relu^2, exact k2; exact-segment form
//    y = tau2 + (dsum - (lam-f2)^2/k2) / (2*lam).
// Warp reductions: single-instruction REDUX (fixed-point sums, order-
// preserving uint map for max). __launch_bounds__(128,10) -> 51-reg cap,
// 10 blocks/SM (62.5% occ).

#define DDIM 1024
#define NDIM 512
#define ABSMASK 0x7FFFFFFF7FFFFFFFULL

typedef unsigned long long u64;

__device__ __forceinline__ u64 f32x2_add(u64 a, u64 b) {
    u64 r; asm("add.rn.f32x2 %0, %1, %2;" : "=l"(r) : "l"(a), "l"(b)); return r;
}
__device__ __forceinline__ u64 f32x2_fma(u64 a, u64 b, u64 c) {
    u64 r; asm("fma.rn.f32x2 %0, %1, %2, %3;" : "=l"(r) : "l"(a), "l"(b), "l"(c)); return r;
}
__device__ __forceinline__ u64 pack2(float lo, float hi) {
    u64 r; asm("mov.b64 %0, {%1, %2};" : "=l"(r) : "f"(lo), "f"(hi)); return r;
}
__device__ __forceinline__ float2 unpack2(u64 v) {
    float2 r; asm("mov.b64 {%0, %1}, %2;" : "=f"(r.x), "=f"(r.y) : "l"(v)); return r;
}
// f32x2 (u64) -> f16x2 (one F2FP.PACK)
__device__ __forceinline__ unsigned cvt_h2(u64 v) {
    float2 f = unpack2(v);
    unsigned h;
    asm("cvt.rn.f16x2.f32 %0, %1, %2;" : "=r"(h) : "f"(f.y), "f"(f.x));
    return h;
}
__device__ __forceinline__ unsigned h2_sub(unsigned a, unsigned b) {
    unsigned r; asm("sub.rn.f16x2 %0, %1, %2;" : "=r"(r) : "r"(a), "r"(b)); return r;
}
__device__ __forceinline__ unsigned h2_max0(unsigned a) {
    unsigned r; asm("max.f16x2 %0, %1, %2;" : "=r"(r) : "r"(a), "r"(0u)); return r;
}
__device__ __forceinline__ unsigned h2_add(unsigned a, unsigned b) {
    unsigned r; asm("add.rn.f16x2 %0, %1, %2;" : "=r"(r) : "r"(a), "r"(b)); return r;
}
// cnt += -(#negative halves among the 4 f16 values in a,b):
// PRMT gathers the 4 sign-carrying high bytes (a:1,3 / b:1,3 with sign replicate),
// dp4a sums the four s8 lanes (each -1 if negative).
__device__ __forceinline__ void h2_sgncnt(unsigned a, unsigned b, int& cnt) {
    unsigned p;
    asm("prmt.b32 %0, %1, %2, 0xFDB9;" : "=r"(p) : "r"(a), "r"(b));
    asm("dp4a.s32.s32 %0, %1, %2, %0;" : "+r"(cnt) : "r"(p), "r"(0x01010101));
}
// cnt += -2 * (#negative floats in packed f32x2 word t)
__device__ __forceinline__ void dp4a_sgn(u64 t, int& cnt) {
    unsigned lo, hi, p;
    asm("mov.b64 {%0, %1}, %2;" : "=r"(lo), "=r"(hi) : "l"(t));
    asm("prmt.b32 %0, %1, %2, 0xFBFB;" : "=r"(p) : "r"(lo), "r"(hi));
    asm("dp4a.s32.s32 %0, %1, %2, %0;" : "+r"(cnt) : "r"(p), "r"(0x01010101));
}
__device__ __forceinline__ float redux_fsum(float v, float scale, float inv) {
    int i = __float2int_rn(v * scale);
    unsigned s = __reduce_add_sync(0xffffffffu, (unsigned)i);
    return (float)(int)s * inv;
}
__device__ __forceinline__ unsigned fmap(float f) {
    unsigned u = __float_as_uint(f);
    return (u & 0x80000000u) ? ~u : (u | 0x80000000u);
}
__device__ __forceinline__ float funmap(unsigned m) {
    unsigned u = (m & 0x80000000u) ? (m ^ 0x80000000u) : ~m;
    return __uint_as_float(u);
}
__device__ __forceinline__ float fast_sqrt(float v) {
    float r; asm("sqrt.approx.f32 %0, %1;" : "=f"(r) : "f"(v)); return r;
}

__global__ __launch_bounds__(128, 10)
void moreau_tropical_kernel(const float* __restrict__ x,
                            const float* __restrict__ W,
                            const float* __restrict__ lamp,
                            float* __restrict__ y,
                            int total_pairs) {
    int warp = (blockIdx.x * 128 + threadIdx.x) >> 5;
    if (warp >= total_pairs) return;
    int lane = threadIdx.x & 31;
    int b = warp >> 9;           // / NDIM
    int n = warp & (NDIM - 1);
    float lam = __ldg(lamp);

    const float4* xr = (const float4*)(x + (size_t)b * DDIM);
    const float4* wr = (const float4*)(W + (size_t)n * DDIM);

    u64 z[16];
    float mx = -3.4e38f;
#pragma unroll
    for (int j = 0; j < 8; j++) {
        float4 xv = xr[lane + 32 * j];
        float4 wv = wr[lane + 32 * j];
        u64 zp0 = f32x2_add(pack2(xv.x, xv.y), pack2(wv.x, wv.y));
        u64 zp1 = f32x2_add(pack2(xv.z, xv.w), pack2(wv.z, wv.w));
        z[2 * j]     = zp0;
        z[2 * j + 1] = zp1;
        float2 a = unpack2(zp0);
        float2 c = unpack2(zp1);
        mx = fmaxf(mx, fmaxf(fmaxf(a.x, a.y), fmaxf(c.x, c.y)));
    }
    mx = funmap(__reduce_max_sync(0xffffffffu, fmap(mx)));

    // Pass 1 (f16x2) @ taua = mx - lam: fa = sum relu(z - taua), ka = count.
    float taua = mx - lam;
    unsigned ta_h;
    asm("cvt.rn.f16x2.f32 %0, %1, %1;" : "=r"(ta_h) : "f"(taua));
    unsigned ha0 = 0u, ha1 = 0u;
    int ca = 0;
#pragma unroll
    for (int j = 0; j < 16; j += 2) {
        unsigned t0 = h2_sub(cvt_h2(z[j + 0]), ta_h);
        unsigned t1 = h2_sub(cvt_h2(z[j + 1]), ta_h);
        ha0 = h2_add(ha0, h2_max0(t0));
        ha1 = h2_add(ha1, h2_max0(t1));
        h2_sgncnt(t0, t1, ca);
    }
    unsigned hsum = h2_add(ha0, ha1);
    __half2 hs = *reinterpret_cast<__half2*>(&hsum);
    float2 fsv = __half22float2(hs);
    float fa = redux_fsum(fsv.x + fsv.y, 1048576.0f, 9.5367431640625e-7f);  // 2^20
    int cta = (int)__reduce_add_sync(0xffffffffu, (unsigned)ca);   // -(#neg)
    float ka = (float)(1024 + cta);                                // >= 1

    // Quadratic-Hermite step: q(taua+s) = fa - ka*s + c*s^2 with q(mx) = 0.
    // Clamp fa to its structural floor (max element contributes >= lam).
    fa = fmaxf(fa, lam);
    ka = fmaxf(ka, 1.0f);
    float fml = fa - lam;
    float c2q = __fdividef(fmaxf(ka * lam - fa, 0.f), lam * lam);
    float disc = fmaf(-4.f * c2q, fml, ka * ka);
    float s = __fdividef(2.f * fml, ka + fast_sqrt(disc));
    float tau2 = fminf(fmaxf(taua + s, taua), mx);

    // Pass 2 (f32, exact) @ tau2: f2, dsum = sum relu^2, k2.
    u64 nt = pack2(-tau2, -tau2);
    u64 us0 = 0ull, q0 = 0ull;
    int cc2 = 0;
#pragma unroll
    for (int j = 0; j < 16; j += 2) {
        u64 t0 = f32x2_add(z[j + 0], nt);
        u64 t1 = f32x2_add(z[j + 1], nt);
        u64 b0 = t0 & ABSMASK;
        u64 b1 = t1 & ABSMASK;
        u64 u0 = f32x2_add(t0, b0);
        u64 u1 = f32x2_add(t1, b1);
        us0 = f32x2_add(us0, f32x2_add(u0, u1));
        q0 = f32x2_fma(u0, u0, q0);
        q0 = f32x2_fma(u1, u1, q0);
        dp4a_sgn(t0, cc2);
        dp4a_sgn(t1, cc2);
    }
    float2 usv = unpack2(us0);
    float2 qv  = unpack2(q0);
    float f2 = 0.5f * redux_fsum(usv.x + usv.y, 1048576.0f, 9.5367431640625e-7f);  // 2^20
    float Us = redux_fsum(qv.x + qv.y, 2097152.0f, 4.76837158203125e-7f);          // 2^21
    int ct2 = (int)__reduce_add_sync(0xffffffffu, (unsigned)cc2);
    float k2 = (float)(1024 + (ct2 >> 1));                         // >= 1

    if (lane == 0) {
        float dsum = 0.25f * Us;
        float d = lam - f2;
        float corr = __fdividef(d * d, k2);
        y[warp] = tau2 + (dsum - corr) * __fdividef(0.5f, lam);
    }
}

extern "C" void kernel_launch(void* const* d_in, const int* in_sizes, int n_in,
                              void* d_out, int out_size) {
    const float* x   = (const float*)d_in[0];
    const float* W   = (const float*)d_in[1];
    const float* lam = (const float*)d_in[2];
    float* y = (float*)d_out;

    int B = in_sizes[0] / DDIM;      // 128
    int N = in_sizes[1] / DDIM;      // 512 (index math assumes 512)
    int pairs = B * N;               // 65536
    int blocks = (pairs + 3) / 4;    // 4 warps / block (128 threads)
    moreau_tropical_kernel<<<blocks, 128>>>(x, W, lam, y, pairs);
}

// round 11
// speedup vs baseline: 1.0656x; 1.0513x over previous
#include <cuda_runtime.h>
#include <cuda_fp16.h>

// MoreauTropicalKernel: B=128, N=512, D=1024. One warp per (b,n) pair.
// z = x[b]+W[n] resident as 16 packed f32x2 registers.
//  Pass1 (f16x2): at taua = mx - lam compute fa = sum relu(z-taua) and slope
//    ka = #{z >= taua} (PRMT sign-gather + dp4a).
//  Quadratic-Hermite root step: parabola through (taua,fa), slope -ka, anchor
//    (mx,0) -> tau2; c = (ka*lam-fa)/lam^2 >= 0 by convexity.
//  Pass2 (f32, exact f2 & dsum): correction slope k via the FREE chord
//    (fa - f2)/(tau2 - taua) instead of an exact count (correction term is
//    ~1e-5 relative; 2x slope error is harmless).
//    y = tau2 + (dsum - (lam-f2)^2/k) / (2*lam).
// Warp reductions: single-instruction REDUX (fixed-point sums, order-
// preserving uint map for max). 96-thread blocks: 14 blocks/SM @ 48 regs
// -> 42 warps/SM (65.6% occ).

#define DDIM 1024
#define NDIM 512
#define ABSMASK 0x7FFFFFFF7FFFFFFFULL

typedef unsigned long long u64;

__device__ __forceinline__ u64 f32x2_add(u64 a, u64 b) {
    u64 r; asm("add.rn.f32x2 %0, %1, %2;" : "=l"(r) : "l"(a), "l"(b)); return r;
}
__device__ __forceinline__ u64 f32x2_fma(u64 a, u64 b, u64 c) {
    u64 r; asm("fma.rn.f32x2 %0, %1, %2, %3;" : "=l"(r) : "l"(a), "l"(b), "l"(c)); return r;
}
__device__ __forceinline__ u64 pack2(float lo, float hi) {
    u64 r; asm("mov.b64 %0, {%1, %2};" : "=l"(r) : "f"(lo), "f"(hi)); return r;
}
__device__ __forceinline__ float2 unpack2(u64 v) {
    float2 r; asm("mov.b64 {%0, %1}, %2;" : "=f"(r.x), "=f"(r.y) : "l"(v)); return r;
}
// f32x2 (u64) -> f16x2 (one F2FP.PACK)
__device__ __forceinline__ unsigned cvt_h2(u64 v) {
    float2 f = unpack2(v);
    unsigned h;
    asm("cvt.rn.f16x2.f32 %0, %1, %2;" : "=r"(h) : "f"(f.y), "f"(f.x));
    return h;
}
__device__ __forceinline__ unsigned h2_sub(unsigned a, unsigned b) {
    unsigned r; asm("sub.rn.f16x2 %0, %1, %2;" : "=r"(r) : "r"(a), "r"(b)); return r;
}
__device__ __forceinline__ unsigned h2_max0(unsigned a) {
    unsigned r; asm("max.f16x2 %0, %1, %2;" : "=r"(r) : "r"(a), "r"(0u)); return r;
}
__device__ __forceinline__ unsigned h2_add(unsigned a, unsigned b) {
    unsigned r; asm("add.rn.f16x2 %0, %1, %2;" : "=r"(r) : "r"(a), "r"(b)); return r;
}
// cnt += -(#negative halves among the 4 f16 values in a,b)
__device__ __forceinline__ void h2_sgncnt(unsigned a, unsigned b, int& cnt) {
    unsigned p;
    asm("prmt.b32 %0, %1, %2, 0xFDB9;" : "=r"(p) : "r"(a), "r"(b));
    asm("dp4a.s32.s32 %0, %1, %2, %0;" : "+r"(cnt) : "r"(p), "r"(0x01010101));
}
__device__ __forceinline__ float redux_fsum(float v, float scale, float inv) {
    int i = __float2int_rn(v * scale);
    unsigned s = __reduce_add_sync(0xffffffffu, (unsigned)i);
    return (float)(int)s * inv;
}
__device__ __forceinline__ unsigned fmap(float f) {
    unsigned u = __float_as_uint(f);
    return (u & 0x80000000u) ? ~u : (u | 0x80000000u);
}
__device__ __forceinline__ float funmap(unsigned m) {
    unsigned u = (m & 0x80000000u) ? (m ^ 0x80000000u) : ~m;
    return __uint_as_float(u);
}
__device__ __forceinline__ float fast_sqrt(float v) {
    float r; asm("sqrt.approx.f32 %0, %1;" : "=f"(r) : "f"(v)); return r;
}

__global__ __launch_bounds__(96)
void moreau_tropical_kernel(const float* __restrict__ x,
                            const float* __restrict__ W,
                            const float* __restrict__ lamp,
                            float* __restrict__ y,
                            int total_pairs) {
    int warp = (blockIdx.x * 96 + threadIdx.x) >> 5;
    if (warp >= total_pairs) return;
    int lane = threadIdx.x & 31;
    int b = warp >> 9;           // / NDIM
    int n = warp & (NDIM - 1);
    float lam = __ldg(lamp);

    const float4* xr = (const float4*)(x + (size_t)b * DDIM);
    const float4* wr = (const float4*)(W + (size_t)n * DDIM);

    u64 z[16];
    float mx = -3.4e38f;
#pragma unroll
    for (int j = 0; j < 8; j++) {
        float4 xv = xr[lane + 32 * j];
        float4 wv = wr[lane + 32 * j];
        u64 zp0 = f32x2_add(pack2(xv.x, xv.y), pack2(wv.x, wv.y));
        u64 zp1 = f32x2_add(pack2(xv.z, xv.w), pack2(wv.z, wv.w));
        z[2 * j]     = zp0;
        z[2 * j + 1] = zp1;
        float2 a = unpack2(zp0);
        float2 c = unpack2(zp1);
        mx = fmaxf(mx, fmaxf(fmaxf(a.x, a.y), fmaxf(c.x, c.y)));
    }
    mx = funmap(__reduce_max_sync(0xffffffffu, fmap(mx)));

    // Pass 1 (f16x2) @ taua = mx - lam: fa = sum relu(z - taua), ka = count.
    float taua = mx - lam;
    unsigned ta_h;
    asm("cvt.rn.f16x2.f32 %0, %1, %1;" : "=r"(ta_h) : "f"(taua));
    unsigned ha0 = 0u, ha1 = 0u;
    int ca = 0;
#pragma unroll
    for (int j = 0; j < 16; j += 2) {
        unsigned t0 = h2_sub(cvt_h2(z[j + 0]), ta_h);
        unsigned t1 = h2_sub(cvt_h2(z[j + 1]), ta_h);
        ha0 = h2_add(ha0, h2_max0(t0));
        ha1 = h2_add(ha1, h2_max0(t1));
        h2_sgncnt(t0, t1, ca);
    }
    unsigned hsum = h2_add(ha0, ha1);
    __half2 hs = *reinterpret_cast<__half2*>(&hsum);
    float2 fsv = __half22float2(hs);
    float fa = redux_fsum(fsv.x + fsv.y, 1048576.0f, 9.5367431640625e-7f);  // 2^20
    int cta = (int)__reduce_add_sync(0xffffffffu, (unsigned)ca);   // -(#neg)
    float ka = fmaxf((float)(1024 + cta), 1.0f);

    // Quadratic-Hermite step: q(taua+s) = fa - ka*s + c*s^2 with q(mx) = 0.
    fa = fmaxf(fa, lam);
    float fml = fa - lam;
    float c2q = __fdividef(fmaxf(ka * lam - fa, 0.f), lam * lam);
    float disc = fmaf(-4.f * c2q, fml, ka * ka);
    float s = __fdividef(2.f * fml, ka + fast_sqrt(disc));
    float tau2 = fminf(fmaxf(taua + s, taua), mx);

    // Pass 2 (f32, exact) @ tau2: f2 = sum relu, dsum = sum relu^2.
    u64 nt = pack2(-tau2, -tau2);
    u64 us0 = 0ull, q0 = 0ull;
#pragma unroll
    for (int j = 0; j < 16; j += 2) {
        u64 t0 = f32x2_add(z[j + 0], nt);
        u64 t1 = f32x2_add(z[j + 1], nt);
        u64 b0 = t0 & ABSMASK;
        u64 b1 = t1 & ABSMASK;
        u64 u0 = f32x2_add(t0, b0);
        u64 u1 = f32x2_add(t1, b1);
        us0 = f32x2_add(us0, f32x2_add(u0, u1));
        q0 = f32x2_fma(u0, u0, q0);
        q0 = f32x2_fma(u1, u1, q0);
    }
    float2 usv = unpack2(us0);
    float2 qv  = unpack2(q0);
    float f2 = 0.5f * redux_fsum(usv.x + usv.y, 1048576.0f, 9.5367431640625e-7f);  // 2^20
    float Us = redux_fsum(qv.x + qv.y, 2097152.0f, 4.76837158203125e-7f);          // 2^21

    if (lane == 0) {
        float dsum = 0.25f * Us;
        // Chord slope over [taua, tau2] (free); correction term is tiny, so a
        // <=2x slope error is harmless. Guard width; if tau2==taua then
        // f2==fa and d = lam-f2 <= 0 with |d| small -> corr negligible anyway.
        float kc = fmaxf(__fdividef(fa - f2, fmaxf(tau2 - taua, 1e-12f)), 1.0f);
        float d = lam - f2;
        float corr = __fdividef(d * d, kc);
        y[warp] = tau2 + (dsum - corr) * __fdividef(0.5f, lam);
    }
}

extern "C" void kernel_launch(void* const* d_in, const int* in_sizes, int n_in,
                              void* d_out, int out_size) {
    const float* x   = (const float*)d_in[0];
    const float* W   = (const float*)d_in[1];
    const float* lam = (const float*)d_in[2];
    float* y = (float*)d_out;

    int B = in_sizes[0] / DDIM;      // 128
    int N = in_sizes[1] / DDIM;      // 512 (index math assumes 512)
    int pairs = B * N;               // 65536
    int blocks = (pairs + 2) / 3;    // 3 warps / block (96 threads)
    moreau_tropical_kernel<<<blocks, 96>>>(x, W, lam, y, pairs);
}

// round 12
// speedup vs baseline: 1.0756x; 1.0093x over previous
#include <cuda_runtime.h>
#include <cuda_fp16.h>

// MoreauTropicalKernel: B=128, N=512, D=1024. One warp per (b,n) pair.
// z = x[b]+W[n] resident as 16 packed f32x2 registers.
//  Pass1 (f16x2): at taua = mx - lam compute fa = sum relu(z-taua) and slope
//    ka = #{z >= taua} (PRMT sign-gather + dp4a).
//  Quadratic-Hermite root step: parabola through (taua,fa), slope -ka, anchor
//    (mx,0) -> tau2; c = (ka*lam-fa)/lam^2 >= 0 by convexity.
//  Pass2 (f32, exact f2 & dsum): correction slope via the FREE chord
//    (fa - f2)/(tau2 - taua); y = tau2 + (dsum - (lam-f2)^2/kc) / (2*lam).
// Warp reductions: single-instruction REDUX (fixed-point sums, order-
// preserving uint map for max).
// __launch_bounds__(128,10): 48-reg cap -> 10 blocks/SM (62.5% occ), and
// 128-thread blocks divide the 65536-pair grid exactly with even SMSP load.

#define DDIM 1024
#define NDIM 512
#define ABSMASK 0x7FFFFFFF7FFFFFFFULL

typedef unsigned long long u64;

__device__ __forceinline__ u64 f32x2_add(u64 a, u64 b) {
    u64 r; asm("add.rn.f32x2 %0, %1, %2;" : "=l"(r) : "l"(a), "l"(b)); return r;
}
__device__ __forceinline__ u64 f32x2_fma(u64 a, u64 b, u64 c) {
    u64 r; asm("fma.rn.f32x2 %0, %1, %2, %3;" : "=l"(r) : "l"(a), "l"(b), "l"(c)); return r;
}
__device__ __forceinline__ u64 pack2(float lo, float hi) {
    u64 r; asm("mov.b64 %0, {%1, %2};" : "=l"(r) : "f"(lo), "f"(hi)); return r;
}
__device__ __forceinline__ float2 unpack2(u64 v) {
    float2 r; asm("mov.b64 {%0, %1}, %2;" : "=f"(r.x), "=f"(r.y) : "l"(v)); return r;
}
// f32x2 (u64) -> f16x2 (one F2FP.PACK)
__device__ __forceinline__ unsigned cvt_h2(u64 v) {
    float2 f = unpack2(v);
    unsigned h;
    asm("cvt.rn.f16x2.f32 %0, %1, %2;" : "=r"(h) : "f"(f.y), "f"(f.x));
    return h;
}
__device__ __forceinline__ unsigned h2_sub(unsigned a, unsigned b) {
    unsigned r; asm("sub.rn.f16x2 %0, %1, %2;" : "=r"(r) : "r"(a), "r"(b)); return r;
}
__device__ __forceinline__ unsigned h2_max0(unsigned a) {
    unsigned r; asm("max.f16x2 %0, %1, %2;" : "=r"(r) : "r"(a), "r"(0u)); return r;
}
__device__ __forceinline__ unsigned h2_add(unsigned a, unsigned b) {
    unsigned r; asm("add.rn.f16x2 %0, %1, %2;" : "=r"(r) : "r"(a), "r"(b)); return r;
}
// cnt += -(#negative halves among the 4 f16 values in a,b)
__device__ __forceinline__ void h2_sgncnt(unsigned a, unsigned b, int& cnt) {
    unsigned p;
    asm("prmt.b32 %0, %1, %2, 0xFDB9;" : "=r"(p) : "r"(a), "r"(b));
    asm("dp4a.s32.s32 %0, %1, %2, %0;" : "+r"(cnt) : "r"(p), "r"(0x01010101));
}
__device__ __forceinline__ float redux_fsum(float v, float scale, float inv) {
    int i = __float2int_rn(v * scale);
    unsigned s = __reduce_add_sync(0xffffffffu, (unsigned)i);
    return (float)(int)s * inv;
}
__device__ __forceinline__ unsigned fmap(float f) {
    unsigned u = __float_as_uint(f);
    return (u & 0x80000000u) ? ~u : (u | 0x80000000u);
}
__device__ __forceinline__ float funmap(unsigned m) {
    unsigned u = (m & 0x80000000u) ? (m ^ 0x80000000u) : ~m;
    return __uint_as_float(u);
}
__device__ __forceinline__ float fast_sqrt(float v) {
    float r; asm("sqrt.approx.f32 %0, %1;" : "=f"(r) : "f"(v)); return r;
}

__global__ __launch_bounds__(128, 10)
void moreau_tropical_kernel(const float* __restrict__ x,
                            const float* __restrict__ W,
                            const float* __restrict__ lamp,
                            float* __restrict__ y,
                            int total_pairs) {
    int warp = (blockIdx.x * 128 + threadIdx.x) >> 5;
    if (warp >= total_pairs) return;
    int lane = threadIdx.x & 31;
    int b = warp >> 9;           // / NDIM
    int n = warp & (NDIM - 1);
    float lam = __ldg(lamp);

    const float4* xr = (const float4*)(x + (size_t)b * DDIM);
    const float4* wr = (const float4*)(W + (size_t)n * DDIM);

    u64 z[16];
    float mx = -3.4e38f;
#pragma unroll
    for (int j = 0; j < 8; j++) {
        float4 xv = xr[lane + 32 * j];
        float4 wv = wr[lane + 32 * j];
        u64 zp0 = f32x2_add(pack2(xv.x, xv.y), pack2(wv.x, wv.y));
        u64 zp1 = f32x2_add(pack2(xv.z, xv.w), pack2(wv.z, wv.w));
        z[2 * j]     = zp0;
        z[2 * j + 1] = zp1;
        float2 a = unpack2(zp0);
        float2 c = unpack2(zp1);
        mx = fmaxf(mx, fmaxf(fmaxf(a.x, a.y), fmaxf(c.x, c.y)));
    }
    mx = funmap(__reduce_max_sync(0xffffffffu, fmap(mx)));

    // Pass 1 (f16x2) @ taua = mx - lam: fa = sum relu(z - taua), ka = count.
    float taua = mx - lam;
    unsigned ta_h;
    asm("cvt.rn.f16x2.f32 %0, %1, %1;" : "=r"(ta_h) : "f"(taua));
    unsigned ha0 = 0u, ha1 = 0u;
    int ca = 0;
#pragma unroll
    for (int j = 0; j < 16; j += 2) {
        unsigned t0 = h2_sub(cvt_h2(z[j + 0]), ta_h);
        unsigned t1 = h2_sub(cvt_h2(z[j + 1]), ta_h);
        ha0 = h2_add(ha0, h2_max0(t0));
        ha1 = h2_add(ha1, h2_max0(t1));
        h2_sgncnt(t0, t1, ca);
    }
    unsigned hsum = h2_add(ha0, ha1);
    __half2 hs = *reinterpret_cast<__half2*>(&hsum);
    float2 fsv = __half22float2(hs);
    float fa = redux_fsum(fsv.x + fsv.y, 1048576.0f, 9.5367431640625e-7f);  // 2^20
    int cta = (int)__reduce_add_sync(0xffffffffu, (unsigned)ca);   // -(#neg)
    float ka = fmaxf((float)(1024 + cta), 1.0f);

    // Quadratic-Hermite step: q(taua+s) = fa - ka*s + c*s^2 with q(mx) = 0.
    fa = fmaxf(fa, lam);
    float fml = fa - lam;
    float c2q = __fdividef(fmaxf(ka * lam - fa, 0.f), lam * lam);
    float disc = fmaf(-4.f * c2q, fml, ka * ka);
    float s = __fdividef(2.f * fml, ka + fast_sqrt(disc));
    float tau2 = fminf(fmaxf(taua + s, taua), mx);

    // Pass 2 (f32, exact) @ tau2: f2 = sum relu, dsum = sum relu^2.
    u64 nt = pack2(-tau2, -tau2);
    u64 us0 = 0ull, q0 = 0ull;
#pragma unroll
    for (int j = 0; j < 16; j += 2) {
        u64 t0 = f32x2_add(z[j + 0], nt);
        u64 t1 = f32x2_add(z[j + 1], nt);
        u64 b0 = t0 & ABSMASK;
        u64 b1 = t1 & ABSMASK;
        u64 u0 = f32x2_add(t0, b0);
        u64 u1 = f32x2_add(t1, b1);
        us0 = f32x2_add(us0, f32x2_add(u0, u1));
        q0 = f32x2_fma(u0, u0, q0);
        q0 = f32x2_fma(u1, u1, q0);
    }
    float2 usv = unpack2(us0);
    float2 qv  = unpack2(q0);
    float f2 = 0.5f * redux_fsum(usv.x + usv.y, 1048576.0f, 9.5367431640625e-7f);  // 2^20
    float Us = redux_fsum(qv.x + qv.y, 2097152.0f, 4.76837158203125e-7f);          // 2^21

    if (lane == 0) {
        float dsum = 0.25f * Us;
        // Chord slope over [taua, tau2] (free). If tau2 ~= taua, f2 ~= fa and
        // d = lam - f2 <= 0 small -> corr negligible regardless.
        float kc = fmaxf(__fdividef(fa - f2, fmaxf(tau2 - taua, 1e-12f)), 1.0f);
        float d = lam - f2;
        float corr = __fdividef(d * d, kc);
        y[warp] = tau2 + (dsum - corr) * __fdividef(0.5f, lam);
    }
}

extern "C" void kernel_launch(void* const* d_in, const int* in_sizes, int n_in,
                              void* d_out, int out_size) {
    const float* x   = (const float*)d_in[0];
    const float* W   = (const float*)d_in[1];
    const float* lam = (const float*)d_in[2];
    float* y = (float*)d_out;

    int B = in_sizes[0] / DDIM;      // 128
    int N = in_sizes[1] / DDIM;      // 512 (index math assumes 512)
    int pairs = B * N;               // 65536
    int blocks = (pairs + 3) / 4;    // 4 warps / block (128 threads), exact
    moreau_tropical_kernel<<<blocks, 128>>>(x, W, lam, y, pairs);
}